// round 1
// baseline (speedup 1.0000x reference)
#include <cuda_runtime.h>
#include <math.h>

#define SEQ_LEN 20
#define NF      812
#define HID     400
#define VARIDX  811
#define BATCH   8192
#define NGATE   (4*HID)     // 1600
#define KREAL   1213        // 812 + 1 + 400
#define KTOT    1216        // padded to multiple of 16

// -------- device scratch (no allocations allowed) --------
__device__ float g_h[BATCH*HID];
__device__ float g_c[BATCH*HID];
__device__ float g_gates[(size_t)BATCH*NGATE];
__device__ float g_WT[KTOT*NGATE];          // K-major packed [W_ih | W_hh | 0]
__device__ float g_xvar[BATCH];
__device__ float g_wsum[HID];
__device__ float g_numbuf[SEQ_LEN][BATCH];  // per-sample loss numerator
__device__ float g_denbuf[SEQ_LEN][BATCH];  // per-sample mask
__device__ float g_stepw[SEQ_LEN];

// -------- init: zero state, w_sum = sum_f W_decay[j,f] --------
__global__ void k_init(const float* __restrict__ W_decay) {
    int idx = blockIdx.x*blockDim.x + threadIdx.x;
    if (idx < BATCH*HID) { g_h[idx] = 0.f; g_c[idx] = 0.f; }
    if (idx < HID) {
        const float* row = W_decay + (size_t)idx*NF;
        float s = 0.f;
        for (int f = 0; f < NF; f++) s += row[f];
        g_wsum[idx] = s;
    }
}

// -------- pack weights K-major: WT[f][g] --------
__global__ void k_pack(const float* __restrict__ W_ih, const float* __restrict__ W_hh) {
    int idx = blockIdx.x*blockDim.x + threadIdx.x;
    if (idx >= KTOT*NGATE) return;
    int f = idx / NGATE, g = idx % NGATE;
    float v;
    if (f < NF+1)        v = W_ih[(size_t)g*(NF+1) + f];
    else if (f < KREAL)  v = W_hh[(size_t)g*HID + (f - (NF+1))];
    else                 v = 0.f;
    g_WT[idx] = v;
}

// -------- per-step: decay h, x_h dot, imputation, loss contributions --------
__global__ void k_decay(const float* __restrict__ values,
                        const float* __restrict__ masks,
                        const float* __restrict__ deltas,
                        const float* __restrict__ b_decay,
                        const float* __restrict__ W_reg,
                        const float* __restrict__ b_reg,
                        float* __restrict__ out_imp, int t) {
    int b = blockIdx.x;
    int tid = threadIdx.x;
    float d = deltas[b*SEQ_LEN + t];
    float m = masks[b*SEQ_LEN + t];
    float dot = 0.f;
    for (int j = tid; j < HID; j += 128) {
        float z = d * g_wsum[j] + b_decay[j];
        float gamma = expf(-fmaxf(z, 0.f));
        float hv = g_h[b*HID + j] * gamma;
        g_h[b*HID + j] = hv;
        dot += hv * W_reg[j];
    }
    __shared__ float red[4];
    #pragma unroll
    for (int o = 16; o > 0; o >>= 1) dot += __shfl_down_sync(0xffffffffu, dot, o);
    if ((tid & 31) == 0) red[tid >> 5] = dot;
    __syncthreads();
    if (tid == 0) {
        float xh = red[0] + red[1] + red[2] + red[3] + b_reg[0];
        float xo = values[((size_t)b*SEQ_LEN + t)*NF + VARIDX];
        float xv = xo*m + (1.f - m)*xh;
        g_xvar[b] = xv;
        out_imp[b*SEQ_LEN + t] = xv;
        g_numbuf[t][b] = m * fabsf(xo - xh);
        g_denbuf[t][b] = m;
    }
}

// -------- fused gates GEMM: gates = [x_mod|m|h] @ WT + b_ih + b_hh --------
// C[8192 x 1600], K = 1216 (padded). Classic 128x128 tile, 8x8/thread.
__global__ void __launch_bounds__(256, 2) k_gemm(
    const float* __restrict__ values, const float* __restrict__ masks,
    const float* __restrict__ b_ih, const float* __restrict__ b_hh, int t)
{
    __shared__ float As[16][128];   // [k][m]
    __shared__ float Bs[16][128];   // [k][n]
    int bn = blockIdx.x;            // 0..12
    int bm = blockIdx.y;            // 0..63
    int tid = threadIdx.x;
    int tx = tid & 15, ty = tid >> 4;
    int rowBase = bm*128, colBase = bn*128;
    float acc[8][8] = {};

    for (int kt = 0; kt < KTOT/16; kt++) {
        int k0 = kt*16;
        // A loads: 16 consecutive k per row -> 64B contiguous per 16 threads
        #pragma unroll
        for (int i = 0; i < 8; i++) {
            int l = i*256 + tid;
            int r = l >> 4;
            int kk = k0 + (l & 15);
            int row = rowBase + r;
            float v;
            if (kk < NF) {
                v = values[((size_t)row*SEQ_LEN + t)*NF + kk];
                if (kk == VARIDX) v = g_xvar[row];
            } else if (kk == NF) {
                v = masks[row*SEQ_LEN + t];
            } else if (kk < KREAL) {
                v = g_h[row*HID + (kk - NF - 1)];
            } else v = 0.f;
            As[l & 15][r] = v;
        }
        // B loads: coalesced along n
        #pragma unroll
        for (int i = 0; i < 8; i++) {
            int l = i*256 + tid;
            int kk = l >> 7, n = l & 127;
            int col = colBase + n;
            Bs[kk][n] = (col < NGATE) ? g_WT[(k0 + kk)*NGATE + col] : 0.f;
        }
        __syncthreads();
        #pragma unroll
        for (int k = 0; k < 16; k++) {
            float a[8], bb[8];
            #pragma unroll
            for (int i = 0; i < 8; i++) a[i]  = As[k][ty*8 + i];
            #pragma unroll
            for (int j = 0; j < 8; j++) bb[j] = Bs[k][tx*8 + j];
            #pragma unroll
            for (int i = 0; i < 8; i++)
                #pragma unroll
                for (int j = 0; j < 8; j++)
                    acc[i][j] += a[i]*bb[j];
        }
        __syncthreads();
    }
    #pragma unroll
    for (int i = 0; i < 8; i++) {
        int row = rowBase + ty*8 + i;
        #pragma unroll
        for (int j = 0; j < 8; j++) {
            int col = colBase + tx*8 + j;
            if (col < NGATE)
                g_gates[(size_t)row*NGATE + col] = acc[i][j] + b_ih[col] + b_hh[col];
        }
    }
}

// -------- LSTM pointwise --------
__global__ void k_lstm() {
    int idx = blockIdx.x*blockDim.x + threadIdx.x;
    if (idx >= BATCH*HID) return;
    int b = idx / HID, j = idx % HID;
    size_t base = (size_t)b*NGATE;
    float ig = g_gates[base + j];
    float fg = g_gates[base + HID + j];
    float gg = g_gates[base + 2*HID + j];
    float og = g_gates[base + 3*HID + j];
    float si = 1.f/(1.f + expf(-ig));
    float sf = 1.f/(1.f + expf(-fg));
    float so = 1.f/(1.f + expf(-og));
    float cv = sf * g_c[idx] + si * tanhf(gg);
    g_c[idx] = cv;
    g_h[idx] = so * tanhf(cv);
}

// -------- deterministic loss reduction --------
__global__ void k_loss1() {
    int t = blockIdx.x;
    int tid = threadIdx.x;
    float sn = 0.f, sd = 0.f;
    for (int b = tid; b < BATCH; b += 256) {  // fixed order per thread
        sn += g_numbuf[t][b];
        sd += g_denbuf[t][b];
    }
    __shared__ float rn[256], rd[256];
    rn[tid] = sn; rd[tid] = sd;
    __syncthreads();
    for (int o = 128; o > 0; o >>= 1) {
        if (tid < o) { rn[tid] += rn[tid+o]; rd[tid] += rd[tid+o]; }
        __syncthreads();
    }
    if (tid == 0) g_stepw[t] = rn[0] / (rd[0] + 1e-5f);
}

__global__ void k_loss2(float* __restrict__ out) {
    if (threadIdx.x == 0 && blockIdx.x == 0) {
        float s = 0.f;
        for (int t = 0; t < SEQ_LEN; t++) s += g_stepw[t];
        out[0] = s / (float)SEQ_LEN;
    }
}

extern "C" void kernel_launch(void* const* d_in, const int* in_sizes, int n_in,
                              void* d_out, int out_size) {
    const float* values  = (const float*)d_in[0];
    const float* masks   = (const float*)d_in[1];
    const float* deltas  = (const float*)d_in[2];
    const float* W_decay = (const float*)d_in[3];
    const float* b_decay = (const float*)d_in[4];
    const float* W_reg   = (const float*)d_in[5];
    const float* b_reg   = (const float*)d_in[6];
    const float* b_ih    = (const float*)d_in[9];
    const float* b_hh    = (const float*)d_in[10];
    const float* W_ih    = (const float*)d_in[7];
    const float* W_hh    = (const float*)d_in[8];
    float* out = (float*)d_out;
    float* out_imp = out + 1;   // out[0] = loss, out[1..] = imputations [B][T]

    k_init<<<(BATCH*HID + 255)/256, 256>>>(W_decay);
    k_pack<<<(KTOT*NGATE + 255)/256, 256>>>(W_ih, W_hh);
    for (int t = 0; t < SEQ_LEN; t++) {
        k_decay<<<BATCH, 128>>>(values, masks, deltas, b_decay, W_reg, b_reg, out_imp, t);
        dim3 grid((NGATE + 127)/128, BATCH/128);
        k_gemm<<<grid, 256>>>(values, masks, b_ih, b_hh, t);
        k_lstm<<<(BATCH*HID + 255)/256, 256>>>();
    }
    k_loss1<<<SEQ_LEN, 256>>>();
    k_loss2<<<1, 32>>>(out);
}

// round 3
// speedup vs baseline: 5.1568x; 5.1568x over previous
#include <cuda_runtime.h>
#include <cstdint>
#include <math.h>

#define SEQ_LEN 20
#define NF      812
#define HID     400
#define VARIDX  811
#define BATCH   8192
#define NGATE   (4*HID)     // 1600
// K layout: [ h 0..399 | pad ..415 | values 416..1227 (1227=xvar) | mask 1228 | pad ..1247 ]
#define KP      1248
#define VBASE   416
#define NCH     39
#define NPCOL   1664        // packed gate cols padded (13 blocks of 128)
#define STRIDE  36          // smem row stride in floats (conflict-free, 16B-aligned)
#define A_BYTES (128*STRIDE*4)
#define BUF_BYTES (2*A_BYTES)
#define SMEM_SZ (2*BUF_BYTES)

// ---------------- device scratch ----------------
__device__ float g_hbuf[2][BATCH*HID];
__device__ float g_c[BATCH*HID];
__device__ float g_Wpack[(size_t)NPCOL*KP];   // tf32-rounded, packed cols
__device__ float g_bias[NGATE];               // [gate*HID + unit]
__device__ float g_xvar[BATCH];
__device__ float g_wsum[HID];
__device__ float g_numbuf[SEQ_LEN][BATCH];
__device__ float g_denbuf[SEQ_LEN][BATCH];
__device__ float g_stepw[SEQ_LEN];

// ---------------- helpers ----------------
__device__ __forceinline__ uint32_t smem_u32(const void* p) {
    uint32_t a;
    asm("{ .reg .u64 t; cvta.to.shared.u64 t, %1; cvt.u32.u64 %0, t; }" : "=r"(a) : "l"(p));
    return a;
}
__device__ __forceinline__ uint32_t f2tf32(float x) {
    uint32_t r; asm("cvt.rna.tf32.f32 %0, %1;" : "=r"(r) : "f"(x)); return r;
}
__device__ __forceinline__ void cp16(uint32_t dst, const void* src, bool valid) {
    if (valid)
        asm volatile("cp.async.ca.shared.global [%0], [%1], 16;" :: "r"(dst), "l"(src));
    else
        asm volatile("cp.async.ca.shared.global [%0], [%1], 16, 0;" :: "r"(dst), "l"(src));
}
__device__ __forceinline__ void mma_tf32(float* c, uint32_t a0, uint32_t a1, uint32_t a2, uint32_t a3,
                                         uint32_t b0, uint32_t b1) {
    asm volatile("mma.sync.aligned.m16n8k8.row.col.f32.tf32.tf32.f32 "
        "{%0,%1,%2,%3}, {%4,%5,%6,%7}, {%8,%9}, {%0,%1,%2,%3};"
        : "+f"(c[0]), "+f"(c[1]), "+f"(c[2]), "+f"(c[3])
        : "r"(a0), "r"(a1), "r"(a2), "r"(a3), "r"(b0), "r"(b1));
}

// ---------------- init ----------------
__global__ void k_init(const float* __restrict__ W_decay) {
    int idx = blockIdx.x*blockDim.x + threadIdx.x;
    if (idx < BATCH*HID) { g_hbuf[0][idx] = 0.f; g_c[idx] = 0.f; }
    if (idx < HID) {
        const float* row = W_decay + (size_t)idx*NF;
        float s = 0.f;
        for (int f = 0; f < NF; f++) s += row[f];
        g_wsum[idx] = s;
    }
}

// ---------------- pack: packed col p -> (gate, unit), K-reordered, tf32-rounded ----------------
// p: blk = p/128, pb = p%128, gate = pb/32, unit = blk*32 + pb%32
__global__ void k_pack(const float* __restrict__ W_ih, const float* __restrict__ W_hh,
                       const float* __restrict__ b_ih, const float* __restrict__ b_hh) {
    int idx = blockIdx.x*blockDim.x + threadIdx.x;
    if (idx < NGATE) g_bias[idx] = b_ih[idx] + b_hh[idx];
    if (idx >= NPCOL*KP) return;
    int p = idx / KP, k = idx % KP;
    int blk = p >> 7, pb = p & 127;
    int gate = pb >> 5, unit = blk*32 + (pb & 31);
    float v = 0.f;
    if (unit < HID) {
        int orig = gate*HID + unit;
        if (k < HID)            v = W_hh[(size_t)orig*HID + k];
        else if (k < VBASE)     v = 0.f;
        else if (k < VBASE+NF)  v = W_ih[(size_t)orig*(NF+1) + (k - VBASE)];
        else if (k == VBASE+NF) v = W_ih[(size_t)orig*(NF+1) + NF];   // mask col
    }
    g_Wpack[idx] = __uint_as_float(f2tf32(v));
}

// ---------------- per-step decay + regression (fp32) ----------------
__global__ void k_decay(const float* __restrict__ values,
                        const float* __restrict__ masks,
                        const float* __restrict__ deltas,
                        const float* __restrict__ b_decay,
                        const float* __restrict__ W_reg,
                        const float* __restrict__ b_reg,
                        float* __restrict__ out_imp, int t) {
    int b = blockIdx.x;
    int tid = threadIdx.x;
    float* h = g_hbuf[t & 1];
    float d = deltas[b*SEQ_LEN + t];
    float m = masks[b*SEQ_LEN + t];
    float dot = 0.f;
    #pragma unroll
    for (int jj = 0; jj < HID; jj += 128) {
        int j = jj + tid;
        if (j < HID) {
            float z = d * g_wsum[j] + b_decay[j];
            float gamma = expf(-fmaxf(z, 0.f));
            float hv = h[b*HID + j] * gamma;
            h[b*HID + j] = hv;
            dot += hv * W_reg[j];
        }
    }
    __shared__ float red[4];
    #pragma unroll
    for (int o = 16; o > 0; o >>= 1) dot += __shfl_down_sync(0xffffffffu, dot, o);
    if ((tid & 31) == 0) red[tid >> 5] = dot;
    __syncthreads();
    if (tid == 0) {
        float xh = red[0] + red[1] + red[2] + red[3] + b_reg[0];
        float xo = values[((size_t)b*SEQ_LEN + t)*NF + VARIDX];
        float xv = xo*m + (1.f - m)*xh;
        g_xvar[b] = xv;
        out_imp[b*SEQ_LEN + t] = xv;
        g_numbuf[t][b] = m * fabsf(xo - xh);
        g_denbuf[t][b] = m;
    }
}

// ---------------- cp.async chunk issue ----------------
__device__ __forceinline__ void issue_chunk(int kt, uint32_t sdst, const float* h_in,
                                            const float* values, int t, int rowBase,
                                            int colBlk, int tid) {
    // A tile: 128 rows x 32 k
    #pragma unroll
    for (int i = 0; i < 4; i++) {
        int idx = i*256 + tid, row = idx >> 3, c4 = idx & 7;
        uint32_t dst = sdst + (uint32_t)(row*STRIDE + c4*4)*4u;
        int rg = rowBase + row;
        const float* src; bool valid;
        if (kt < 13)      { int k = kt*32 + c4*4; src = h_in + (size_t)rg*HID + k; valid = (k < HID); }
        else if (kt < 38) { int v = kt*32 - VBASE + c4*4; src = values + ((size_t)rg*SEQ_LEN + t)*NF + v; valid = true; }
        else              { int v = 800 + c4*4; src = values + ((size_t)rg*SEQ_LEN + t)*NF + v; valid = (c4 < 3); }
        cp16(dst, src, valid);
    }
    // B tile: 128 cols x 32 k
    #pragma unroll
    for (int i = 0; i < 4; i++) {
        int idx = i*256 + tid, col = idx >> 3, c4 = idx & 7;
        uint32_t dst = sdst + (uint32_t)A_BYTES + (uint32_t)(col*STRIDE + c4*4)*4u;
        cp16(dst, &g_Wpack[(size_t)(colBlk*128 + col)*KP + kt*32 + c4*4], true);
    }
    asm volatile("cp.async.commit_group;" ::: "memory");
}

// ---------------- tf32 mma GEMM + fused LSTM epilogue ----------------
// CTA tile M=128 x N=128 packed cols, 8 warps each m16 x n128.
__global__ void __launch_bounds__(256, 2) k_gemm(
    const float* __restrict__ values, const float* __restrict__ masks, int t)
{
    extern __shared__ char smem[];
    float* sm = (float*)smem;
    uint32_t sb = smem_u32(smem);
    int tid = threadIdx.x;
    int warp = tid >> 5, lane = tid & 31, q = lane & 3, rq = lane >> 2;
    int rowBase = blockIdx.y * 128;
    int colBlk = blockIdx.x;
    const float* h_in = g_hbuf[t & 1];
    float* h_out = g_hbuf[(t + 1) & 1];

    float acc[16][4];
    #pragma unroll
    for (int i = 0; i < 16; i++)
        #pragma unroll
        for (int j = 0; j < 4; j++) acc[i][j] = 0.f;

    issue_chunk(0, sb, h_in, values, t, rowBase, colBlk, tid);

    #pragma unroll 1
    for (int kt = 0; kt < NCH; kt++) {
        int buf = kt & 1;
        asm volatile("cp.async.wait_group 0;" ::: "memory");
        __syncthreads();
        if (kt < NCH-1)
            issue_chunk(kt+1, sb + (uint32_t)((buf^1)*BUF_BYTES), h_in, values, t, rowBase, colBlk, tid);
        if (kt == NCH-1) {
            if (tid < 128) {   // patch xvar (k=1227 -> word 11) and mask (k=1228 -> word 12)
                int rg = rowBase + tid;
                sm[buf*(BUF_BYTES/4) + tid*STRIDE + 11] = g_xvar[rg];
                sm[buf*(BUF_BYTES/4) + tid*STRIDE + 12] = masks[rg*SEQ_LEN + t];
            }
            __syncthreads();
        }
        const float* As = sm + buf*(BUF_BYTES/4);
        const float* Bs = As + A_BYTES/4;
        int arow = warp*16 + rq;
        #pragma unroll
        for (int s = 0; s < 4; s++) {
            int k8 = s*8;
            uint32_t a0 = f2tf32(As[arow*STRIDE + k8 + q]);
            uint32_t a1 = f2tf32(As[(arow+8)*STRIDE + k8 + q]);
            uint32_t a2 = f2tf32(As[arow*STRIDE + k8 + q + 4]);
            uint32_t a3 = f2tf32(As[(arow+8)*STRIDE + k8 + q + 4]);
            #pragma unroll
            for (int nf = 0; nf < 16; nf++) {
                uint32_t b0 = __float_as_uint(Bs[(nf*8 + rq)*STRIDE + k8 + q]);
                uint32_t b1 = __float_as_uint(Bs[(nf*8 + rq)*STRIDE + k8 + q + 4]);
                mma_tf32(acc[nf], a0, a1, a2, a3, b0, b1);
            }
        }
    }

    // ---- fused LSTM epilogue ----
    // C frag: rows {warp*16+rq, +8}; cols nf*8 + 2q (+1). col pb = gate*32 + sub*8 + c
    // => nf = gate*4 + sub, c = 2q (+1). unit = colBlk*32 + sub*8 + c.
    int row0 = rowBase + warp*16 + rq;
    #pragma unroll
    for (int sub = 0; sub < 4; sub++) {
        int u0 = colBlk*32 + sub*8 + 2*q;   // even unit; pair (u0, u0+1)
        if (u0 >= HID) continue;
        float2 bi = *(const float2*)&g_bias[u0];
        float2 bf = *(const float2*)&g_bias[HID + u0];
        float2 bg = *(const float2*)&g_bias[2*HID + u0];
        float2 bo = *(const float2*)&g_bias[3*HID + u0];
        #pragma unroll
        for (int r = 0; r < 2; r++) {
            int row = row0 + r*8;
            float ig0 = acc[0*4+sub][r*2+0] + bi.x, ig1 = acc[0*4+sub][r*2+1] + bi.y;
            float fg0 = acc[1*4+sub][r*2+0] + bf.x, fg1 = acc[1*4+sub][r*2+1] + bf.y;
            float gg0 = acc[2*4+sub][r*2+0] + bg.x, gg1 = acc[2*4+sub][r*2+1] + bg.y;
            float og0 = acc[3*4+sub][r*2+0] + bo.x, og1 = acc[3*4+sub][r*2+1] + bo.y;
            float2 cin = *(float2*)&g_c[(size_t)row*HID + u0];
            float si0 = 1.f/(1.f + expf(-ig0)), si1 = 1.f/(1.f + expf(-ig1));
            float sf0 = 1.f/(1.f + expf(-fg0)), sf1 = 1.f/(1.f + expf(-fg1));
            float so0 = 1.f/(1.f + expf(-og0)), so1 = 1.f/(1.f + expf(-og1));
            float c0 = sf0*cin.x + si0*tanhf(gg0);
            float c1 = sf1*cin.y + si1*tanhf(gg1);
            float h0 = so0*tanhf(c0);
            float h1 = so1*tanhf(c1);
            *(float2*)&g_c[(size_t)row*HID + u0]   = make_float2(c0, c1);
            *(float2*)&h_out[(size_t)row*HID + u0] = make_float2(h0, h1);
        }
    }
}

// ---------------- deterministic loss reduction ----------------
__global__ void k_loss1() {
    int t = blockIdx.x, tid = threadIdx.x;
    float sn = 0.f, sd = 0.f;
    for (int b = tid; b < BATCH; b += 256) { sn += g_numbuf[t][b]; sd += g_denbuf[t][b]; }
    __shared__ float rn[256], rd[256];
    rn[tid] = sn; rd[tid] = sd;
    __syncthreads();
    for (int o = 128; o > 0; o >>= 1) {
        if (tid < o) { rn[tid] += rn[tid+o]; rd[tid] += rd[tid+o]; }
        __syncthreads();
    }
    if (tid == 0) g_stepw[t] = rn[0] / (rd[0] + 1e-5f);
}
__global__ void k_loss2(float* __restrict__ out) {
    if (threadIdx.x == 0 && blockIdx.x == 0) {
        float s = 0.f;
        for (int t = 0; t < SEQ_LEN; t++) s += g_stepw[t];
        out[0] = s / (float)SEQ_LEN;
    }
}

extern "C" void kernel_launch(void* const* d_in, const int* in_sizes, int n_in,
                              void* d_out, int out_size) {
    const float* values  = (const float*)d_in[0];
    const float* masks   = (const float*)d_in[1];
    const float* deltas  = (const float*)d_in[2];
    const float* W_decay = (const float*)d_in[3];
    const float* b_decay = (const float*)d_in[4];
    const float* W_reg   = (const float*)d_in[5];
    const float* b_reg   = (const float*)d_in[6];
    const float* W_ih    = (const float*)d_in[7];
    const float* W_hh    = (const float*)d_in[8];
    const float* b_ih    = (const float*)d_in[9];
    const float* b_hh    = (const float*)d_in[10];
    float* out = (float*)d_out;
    float* out_imp = out + 1;

    static bool attr_set = false;
    if (!attr_set) {
        cudaFuncSetAttribute(k_gemm, cudaFuncAttributeMaxDynamicSharedMemorySize, SMEM_SZ);
        attr_set = true;
    }

    k_init<<<(BATCH*HID + 255)/256, 256>>>(W_decay);
    k_pack<<<((size_t)NPCOL*KP + 255)/256, 256>>>(W_ih, W_hh, b_ih, b_hh);
    for (int t = 0; t < SEQ_LEN; t++) {
        k_decay<<<BATCH, 128>>>(values, masks, deltas, b_decay, W_reg, b_reg, out_imp, t);
        dim3 grid(NPCOL/128, BATCH/128);   // (13, 64)
        k_gemm<<<grid, 256, SMEM_SZ>>>(values, masks, t);
    }
    k_loss1<<<SEQ_LEN, 256>>>();
    k_loss2<<<1, 32>>>(out);
}

// round 4
// speedup vs baseline: 7.5343x; 1.4610x over previous
#include <cuda_runtime.h>
#include <cuda_bf16.h>
#include <cstdint>
#include <math.h>

#define SEQ_LEN 20
#define NF      812
#define HID     400
#define VARIDX  811
#define BATCH   8192
#define NGATE   (4*HID)
// K layout: [ h 0..399 | pad ..415 | values 416..1227 (1227=xvar) | mask 1228 | pad ..1247 ]
#define KP      1248
#define NCH     39
#define NPCOL   1664        // 13 blocks of 128 packed cols
#define VW      832         // prepacked values row width (26 chunks of 32)
#define HW      416         // prepacked h row width (13 chunks of 32)
#define AW      20          // smem words per 32-k row (80B, conflict-free)
#define ABYTES  (128*AW*4)  // 10240
#define BUFB    (2*ABYTES)  // A + B
#define SMEMSZ  (2*BUFB)    // double buffered = 40960

// ---------------- device scratch ----------------
__device__ float g_hbuf[2][BATCH*HID];            // fp32 LSTM h state
__device__ float g_c[BATCH*HID];
__device__ __nv_bfloat16 g_hbf[BATCH*HW];         // decayed h, bf16 (GEMM A, chunks 0..12)
__device__ __nv_bfloat16 g_vbf[(size_t)SEQ_LEN*BATCH*VW];  // values+mask bf16 (chunks 13..38)
__device__ __nv_bfloat16 g_Wbf[(size_t)NPCOL*KP]; // packed weights bf16
__device__ float g_bias[NGATE];                   // [gate*HID + unit]
__device__ float g_xvar[BATCH];
__device__ float g_wsum[HID];
__device__ float g_numbuf[SEQ_LEN][BATCH];
__device__ float g_denbuf[SEQ_LEN][BATCH];
__device__ float g_stepw[SEQ_LEN];

// ---------------- helpers ----------------
__device__ __forceinline__ uint32_t smem_u32(const void* p) {
    uint32_t a;
    asm("{ .reg .u64 t; cvta.to.shared.u64 t, %1; cvt.u32.u64 %0, t; }" : "=r"(a) : "l"(p));
    return a;
}
__device__ __forceinline__ void cp16(uint32_t dst, const void* src) {
    asm volatile("cp.async.ca.shared.global [%0], [%1], 16;" :: "r"(dst), "l"(src));
}
__device__ __forceinline__ void mma_bf16(float* c, uint32_t a0, uint32_t a1, uint32_t a2, uint32_t a3,
                                         uint32_t b0, uint32_t b1) {
    asm volatile("mma.sync.aligned.m16n8k16.row.col.f32.bf16.bf16.f32 "
        "{%0,%1,%2,%3}, {%4,%5,%6,%7}, {%8,%9}, {%0,%1,%2,%3};"
        : "+f"(c[0]), "+f"(c[1]), "+f"(c[2]), "+f"(c[3])
        : "r"(a0), "r"(a1), "r"(a2), "r"(a3), "r"(b0), "r"(b1));
}

// ---------------- init ----------------
__global__ void k_init(const float* __restrict__ W_decay) {
    int idx = blockIdx.x*blockDim.x + threadIdx.x;
    if (idx < BATCH*HID) { g_hbuf[0][idx] = 0.f; g_c[idx] = 0.f; }
    if (idx < BATCH*HW)  g_hbf[idx] = __float2bfloat16(0.f);
    if (idx < HID) {
        const float* row = W_decay + (size_t)idx*NF;
        float s = 0.f;
        for (int f = 0; f < NF; f++) s += row[f];
        g_wsum[idx] = s;
    }
}

// ---------------- prepack values+mask to bf16, time-major ----------------
__global__ void k_vpack(const float* __restrict__ values, const float* __restrict__ masks) {
    size_t idx = (size_t)blockIdx.x*blockDim.x + threadIdx.x;
    if (idx >= (size_t)SEQ_LEN*BATCH*VW) return;
    int v = idx % VW;
    size_t r = idx / VW;
    int b = r % BATCH, t = r / BATCH;
    float x;
    if (v < NF)       x = values[((size_t)b*SEQ_LEN + t)*NF + v];
    else if (v == NF) x = masks[b*SEQ_LEN + t];
    else              x = 0.f;
    g_vbf[idx] = __float2bfloat16(x);
}

// ---------------- pack weights: fragment-epilogue-friendly permutation ----------------
// packed col p: colBlk = p>>7, pb = p&127, wn = pb>>6, r = pb&63, nf = r>>3, c = r&7
// gate = nf>>1, sb = nf&1, unit = colBlk*32 + wn*16 + sb*8 + c
__global__ void k_pack(const float* __restrict__ W_ih, const float* __restrict__ W_hh,
                       const float* __restrict__ b_ih, const float* __restrict__ b_hh) {
    size_t idx = (size_t)blockIdx.x*blockDim.x + threadIdx.x;
    if (idx < NGATE) g_bias[idx] = b_ih[idx] + b_hh[idx];
    if (idx >= (size_t)NPCOL*KP) return;
    int p = idx / KP, k = idx % KP;
    int colBlk = p >> 7, pb = p & 127;
    int wn = pb >> 6, r = pb & 63, nf = r >> 3, c = r & 7;
    int gate = nf >> 1, sb = nf & 1;
    int unit = colBlk*32 + wn*16 + sb*8 + c;
    float v = 0.f;
    if (unit < HID) {
        int orig = gate*HID + unit;
        if (k < HID)             v = W_hh[(size_t)orig*HID + k];
        else if (k < HW)         v = 0.f;
        else if (k < HW+NF)      v = W_ih[(size_t)orig*(NF+1) + (k - HW)];
        else if (k == HW+NF)     v = W_ih[(size_t)orig*(NF+1) + NF];   // mask col
    }
    g_Wbf[idx] = __float2bfloat16(v);
}

// ---------------- per-step decay + regression (fp32 state, bf16 GEMM feed) ----------------
__global__ void k_decay(const float* __restrict__ values,
                        const float* __restrict__ masks,
                        const float* __restrict__ deltas,
                        const float* __restrict__ b_decay,
                        const float* __restrict__ W_reg,
                        const float* __restrict__ b_reg,
                        float* __restrict__ out_imp, int t) {
    int b = blockIdx.x;
    int tid = threadIdx.x;
    const float* h = g_hbuf[t & 1];
    float d = deltas[b*SEQ_LEN + t];
    float m = masks[b*SEQ_LEN + t];
    float dot = 0.f;
    #pragma unroll
    for (int jj = 0; jj < HID; jj += 128) {
        int j = jj + tid;
        if (j < HID) {
            float z = d * g_wsum[j] + b_decay[j];
            float gamma = expf(-fmaxf(z, 0.f));
            float hv = h[b*HID + j] * gamma;
            g_hbf[(size_t)b*HW + j] = __float2bfloat16(hv);
            dot += hv * W_reg[j];
        }
    }
    __shared__ float red[4];
    #pragma unroll
    for (int o = 16; o > 0; o >>= 1) dot += __shfl_down_sync(0xffffffffu, dot, o);
    if ((tid & 31) == 0) red[tid >> 5] = dot;
    __syncthreads();
    if (tid == 0) {
        float xh = red[0] + red[1] + red[2] + red[3] + b_reg[0];
        float xo = values[((size_t)b*SEQ_LEN + t)*NF + VARIDX];
        float xv = xo*m + (1.f - m)*xh;
        g_xvar[b] = xv;
        out_imp[b*SEQ_LEN + t] = xv;
        g_numbuf[t][b] = m * fabsf(xo - xh);
        g_denbuf[t][b] = m;
    }
}

// ---------------- cp.async chunk (32 k bf16 = 64B/row, no predicates) ----------------
__device__ __forceinline__ void issue_chunk(int kt, uint32_t sdst, int rowBase,
                                            int colBlk, int t, int tid) {
    #pragma unroll
    for (int i = 0; i < 2; i++) {           // A: 128 rows x 4 x 16B
        int idx = i*256 + tid, row = idx >> 2, c4 = idx & 3;
        uint32_t dst = sdst + (uint32_t)(row*80 + c4*16);
        const __nv_bfloat16* src;
        if (kt < 13) src = g_hbf + (size_t)(rowBase + row)*HW + kt*32 + c4*8;
        else         src = g_vbf + ((size_t)t*BATCH + rowBase + row)*VW + (kt-13)*32 + c4*8;
        cp16(dst, src);
    }
    #pragma unroll
    for (int i = 0; i < 2; i++) {           // B: 128 cols x 4 x 16B
        int idx = i*256 + tid, col = idx >> 2, c4 = idx & 3;
        uint32_t dst = sdst + (uint32_t)ABYTES + (uint32_t)(col*80 + c4*16);
        cp16(dst, g_Wbf + (size_t)(colBlk*128 + col)*KP + kt*32 + c4*8);
    }
    asm volatile("cp.async.commit_group;" ::: "memory");
}

// ---------------- bf16 mma GEMM + fused LSTM epilogue ----------------
// CTA 128x128 packed cols; 8 warps as 4(M) x 2(N); warp tile m32 x n64.
__global__ void __launch_bounds__(256, 2) k_gemm(const float* __restrict__ masks, int t)
{
    extern __shared__ char smem[];
    uint32_t sb = smem_u32(smem);
    int tid = threadIdx.x;
    int warp = tid >> 5, lane = tid & 31, q = lane & 3, rq = lane >> 2;
    int wm = warp & 3, wn = warp >> 2;
    int rowBase = blockIdx.y * 128;
    int colBlk = blockIdx.x;
    float* h_out = g_hbuf[(t + 1) & 1];

    float acc[2][8][4];
    #pragma unroll
    for (int mi = 0; mi < 2; mi++)
        #pragma unroll
        for (int nf = 0; nf < 8; nf++)
            #pragma unroll
            for (int j = 0; j < 4; j++) acc[mi][nf][j] = 0.f;

    issue_chunk(0, sb, rowBase, colBlk, t, tid);

    #pragma unroll 1
    for (int kt = 0; kt < NCH; kt++) {
        int buf = kt & 1;
        asm volatile("cp.async.wait_group 0;" ::: "memory");
        __syncthreads();
        if (kt < NCH-1)
            issue_chunk(kt+1, sb + (uint32_t)((buf^1)*BUFB), rowBase, colBlk, t, tid);
        if (kt == NCH-1) {
            if (tid < 128) {  // patch xvar: chunk-38 local bf16 index 11
                *(__nv_bfloat16*)(smem + buf*BUFB + tid*80 + 22) =
                    __float2bfloat16(g_xvar[rowBase + tid]);
            }
            __syncthreads();
        }
        const uint32_t* As = (const uint32_t*)(smem + buf*BUFB);
        const uint32_t* Bs = As + ABYTES/4;
        #pragma unroll
        for (int s = 0; s < 2; s++) {
            int kw = s*8;
            uint32_t breg[8][2];
            #pragma unroll
            for (int nf = 0; nf < 8; nf++) {
                int n = wn*64 + nf*8 + rq;
                breg[nf][0] = Bs[n*AW + kw + q];
                breg[nf][1] = Bs[n*AW + kw + q + 4];
            }
            #pragma unroll
            for (int mi = 0; mi < 2; mi++) {
                int ar = wm*32 + mi*16 + rq;
                uint32_t a0 = As[ar*AW + kw + q];
                uint32_t a1 = As[(ar+8)*AW + kw + q];
                uint32_t a2 = As[ar*AW + kw + q + 4];
                uint32_t a3 = As[(ar+8)*AW + kw + q + 4];
                #pragma unroll
                for (int nf = 0; nf < 8; nf++)
                    mma_bf16(acc[mi][nf], a0, a1, a2, a3, breg[nf][0], breg[nf][1]);
            }
        }
    }

    // ---- fused LSTM epilogue: thread owns units u0,u0+1 per sb; gates at nf=gate*2+sb ----
    int row_b = rowBase + wm*32 + rq;
    #pragma unroll
    for (int sbx = 0; sbx < 2; sbx++) {
        int u0 = colBlk*32 + wn*16 + sbx*8 + 2*q;
        if (u0 >= HID) continue;
        float2 bi = *(const float2*)&g_bias[u0];
        float2 bf_ = *(const float2*)&g_bias[HID + u0];
        float2 bg = *(const float2*)&g_bias[2*HID + u0];
        float2 bo = *(const float2*)&g_bias[3*HID + u0];
        #pragma unroll
        for (int mi = 0; mi < 2; mi++) {
            #pragma unroll
            for (int r = 0; r < 2; r++) {
                int row = row_b + mi*16 + r*8;
                int e = r*2;
                float ig0 = acc[mi][0+sbx][e]   + bi.x, ig1 = acc[mi][0+sbx][e+1] + bi.y;
                float fg0 = acc[mi][2+sbx][e]   + bf_.x, fg1 = acc[mi][2+sbx][e+1] + bf_.y;
                float gg0 = acc[mi][4+sbx][e]   + bg.x, gg1 = acc[mi][4+sbx][e+1] + bg.y;
                float og0 = acc[mi][6+sbx][e]   + bo.x, og1 = acc[mi][6+sbx][e+1] + bo.y;
                float2 cin = *(float2*)&g_c[(size_t)row*HID + u0];
                float si0 = 1.f/(1.f + expf(-ig0)), si1 = 1.f/(1.f + expf(-ig1));
                float sf0 = 1.f/(1.f + expf(-fg0)), sf1 = 1.f/(1.f + expf(-fg1));
                float so0 = 1.f/(1.f + expf(-og0)), so1 = 1.f/(1.f + expf(-og1));
                float c0 = sf0*cin.x + si0*tanhf(gg0);
                float c1 = sf1*cin.y + si1*tanhf(gg1);
                *(float2*)&g_c[(size_t)row*HID + u0]   = make_float2(c0, c1);
                *(float2*)&h_out[(size_t)row*HID + u0] = make_float2(so0*tanhf(c0), so1*tanhf(c1));
            }
        }
    }
}

// ---------------- deterministic loss reduction ----------------
__global__ void k_loss1() {
    int t = blockIdx.x, tid = threadIdx.x;
    float sn = 0.f, sd = 0.f;
    for (int b = tid; b < BATCH; b += 256) { sn += g_numbuf[t][b]; sd += g_denbuf[t][b]; }
    __shared__ float rn[256], rd[256];
    rn[tid] = sn; rd[tid] = sd;
    __syncthreads();
    for (int o = 128; o > 0; o >>= 1) {
        if (tid < o) { rn[tid] += rn[tid+o]; rd[tid] += rd[tid+o]; }
        __syncthreads();
    }
    if (tid == 0) g_stepw[t] = rn[0] / (rd[0] + 1e-5f);
}
__global__ void k_loss2(float* __restrict__ out) {
    if (threadIdx.x == 0 && blockIdx.x == 0) {
        float s = 0.f;
        for (int t = 0; t < SEQ_LEN; t++) s += g_stepw[t];
        out[0] = s / (float)SEQ_LEN;
    }
}

extern "C" void kernel_launch(void* const* d_in, const int* in_sizes, int n_in,
                              void* d_out, int out_size) {
    const float* values  = (const float*)d_in[0];
    const float* masks   = (const float*)d_in[1];
    const float* deltas  = (const float*)d_in[2];
    const float* W_decay = (const float*)d_in[3];
    const float* b_decay = (const float*)d_in[4];
    const float* W_reg   = (const float*)d_in[5];
    const float* b_reg   = (const float*)d_in[6];
    const float* W_ih    = (const float*)d_in[7];
    const float* W_hh    = (const float*)d_in[8];
    const float* b_ih    = (const float*)d_in[9];
    const float* b_hh    = (const float*)d_in[10];
    float* out = (float*)d_out;
    float* out_imp = out + 1;

    k_init<<<(BATCH*HID + 255)/256, 256>>>(W_decay);
    k_vpack<<<(int)(((size_t)SEQ_LEN*BATCH*VW + 255)/256), 256>>>(values, masks);
    k_pack<<<(int)(((size_t)NPCOL*KP + 255)/256), 256>>>(W_ih, W_hh, b_ih, b_hh);
    for (int t = 0; t < SEQ_LEN; t++) {
        k_decay<<<BATCH, 128>>>(values, masks, deltas, b_decay, W_reg, b_reg, out_imp, t);
        dim3 grid(NPCOL/128, BATCH/128);   // (13, 64)
        k_gemm<<<grid, 256, SMEMSZ>>>(masks, t);
    }
    k_loss1<<<SEQ_LEN, 256>>>();
    k_loss2<<<1, 32>>>(out);
}

// round 6
// speedup vs baseline: 7.9544x; 1.0558x over previous
#include <cuda_runtime.h>
#include <cuda_bf16.h>
#include <cstdint>
#include <math.h>

#define SEQ_LEN 20
#define NF      812
#define HID     400
#define VARIDX  811
#define BATCH   8192
#define NGATE   (4*HID)
// K layout: [ h 0..399 | pad ..415 | values 416..1227 (1227=xvar) | mask 1228 | pad ..1247 ]
#define KP      1248
#define NCH     39
#define NPCOL   1664        // 13 blocks of 128 packed cols
#define VW      832         // prepacked values row width (26 chunks of 32)
#define HW      416         // prepacked h row width (13 chunks of 32)
#define AW      20          // smem words per 32-k row (80B, conflict-free rows)
#define ABYTES  (128*AW*4)  // 10240
#define BUFB    (2*ABYTES)  // A + B = 20480
#define STAGES  4
#define SMEMSZ  (STAGES*BUFB)  // 81920

// ---------------- device scratch ----------------
__device__ float g_hbuf[2][BATCH*HID];            // fp32 LSTM h state
__device__ float g_c[BATCH*HID];
__device__ __nv_bfloat16 g_hbf[BATCH*HW];         // decayed h bf16 (chunks 0..12)
__device__ __nv_bfloat16 g_vbf[(size_t)SEQ_LEN*BATCH*VW];  // values+mask bf16 (chunks 13..38)
__device__ __nv_bfloat16 g_Wbf[(size_t)NPCOL*KP]; // packed weights bf16
__device__ float g_bias[NGATE];
__device__ float g_xvar[BATCH];
__device__ float g_wsum[HID];
__device__ float g_numbuf[SEQ_LEN][BATCH];
__device__ float g_denbuf[SEQ_LEN][BATCH];
__device__ float g_stepw[SEQ_LEN];

// ---------------- helpers ----------------
__device__ __forceinline__ uint32_t smem_u32(const void* p) {
    uint32_t a;
    asm("{ .reg .u64 t; cvta.to.shared.u64 t, %1; cvt.u32.u64 %0, t; }" : "=r"(a) : "l"(p));
    return a;
}
__device__ __forceinline__ void cp16(uint32_t dst, const void* src) {
    asm volatile("cp.async.cg.shared.global [%0], [%1], 16;" :: "r"(dst), "l"(src));
}
__device__ __forceinline__ void ldsm4(uint32_t& r0, uint32_t& r1, uint32_t& r2, uint32_t& r3,
                                      uint32_t addr) {
    asm volatile("ldmatrix.sync.aligned.m8n8.x4.shared.b16 {%0,%1,%2,%3}, [%4];"
        : "=r"(r0), "=r"(r1), "=r"(r2), "=r"(r3) : "r"(addr));
}
__device__ __forceinline__ void mma_bf16(float* c, uint32_t a0, uint32_t a1, uint32_t a2, uint32_t a3,
                                         uint32_t b0, uint32_t b1) {
    asm volatile("mma.sync.aligned.m16n8k16.row.col.f32.bf16.bf16.f32 "
        "{%0,%1,%2,%3}, {%4,%5,%6,%7}, {%8,%9}, {%0,%1,%2,%3};"
        : "+f"(c[0]), "+f"(c[1]), "+f"(c[2]), "+f"(c[3])
        : "r"(a0), "r"(a1), "r"(a2), "r"(a3), "r"(b0), "r"(b1));
}

// ---------------- init ----------------
__global__ void k_init(const float* __restrict__ W_decay) {
    int idx = blockIdx.x*blockDim.x + threadIdx.x;
    if (idx < BATCH*HID) { g_hbuf[0][idx] = 0.f; g_c[idx] = 0.f; }
    if (idx < BATCH*HW)  g_hbf[idx] = __float2bfloat16(0.f);
    if (idx < HID) {
        const float* row = W_decay + (size_t)idx*NF;
        float s = 0.f;
        for (int f = 0; f < NF; f++) s += row[f];
        g_wsum[idx] = s;
    }
}

// ---------------- prepack values+mask to bf16, time-major ----------------
__global__ void k_vpack(const float* __restrict__ values, const float* __restrict__ masks) {
    size_t idx = (size_t)blockIdx.x*blockDim.x + threadIdx.x;
    if (idx >= (size_t)SEQ_LEN*BATCH*VW) return;
    int v = idx % VW;
    size_t r = idx / VW;
    int b = r % BATCH, t = r / BATCH;
    float x;
    if (v < NF)       x = values[((size_t)b*SEQ_LEN + t)*NF + v];
    else if (v == NF) x = masks[b*SEQ_LEN + t];
    else              x = 0.f;
    g_vbf[idx] = __float2bfloat16(x);
}

// ---------------- pack weights (same permutation as R4) ----------------
__global__ void k_pack(const float* __restrict__ W_ih, const float* __restrict__ W_hh,
                       const float* __restrict__ b_ih, const float* __restrict__ b_hh) {
    size_t idx = (size_t)blockIdx.x*blockDim.x + threadIdx.x;
    if (idx < NGATE) g_bias[idx] = b_ih[idx] + b_hh[idx];
    if (idx >= (size_t)NPCOL*KP) return;
    int p = idx / KP, k = idx % KP;
    int colBlk = p >> 7, pb = p & 127;
    int wn = pb >> 6, r = pb & 63, nf = r >> 3, c = r & 7;
    int gate = nf >> 1, sb = nf & 1;
    int unit = colBlk*32 + wn*16 + sb*8 + c;
    float v = 0.f;
    if (unit < HID) {
        int orig = gate*HID + unit;
        if (k < HID)          v = W_hh[(size_t)orig*HID + k];
        else if (k < HW)      v = 0.f;
        else if (k < HW+NF)   v = W_ih[(size_t)orig*(NF+1) + (k - HW)];
        else if (k == HW+NF)  v = W_ih[(size_t)orig*(NF+1) + NF];   // mask col
    }
    g_Wbf[idx] = __float2bfloat16(v);
}

// ---------------- per-step decay + regression: warp-per-row ----------------
__global__ void __launch_bounds__(256) k_decay(
    const float* __restrict__ values, const float* __restrict__ masks,
    const float* __restrict__ deltas, const float* __restrict__ b_decay,
    const float* __restrict__ W_reg, const float* __restrict__ b_reg,
    float* __restrict__ out_imp, int t)
{
    int warp = threadIdx.x >> 5, lane = threadIdx.x & 31;
    int b = blockIdx.x*8 + warp;
    const float* h = g_hbuf[t & 1];
    float d = deltas[b*SEQ_LEN + t];
    float m = masks[b*SEQ_LEN + t];
    float dot = 0.f;
    #pragma unroll
    for (int jj = 0; jj < HID; jj += 32) {
        int j = jj + lane;
        if (j < HID) {
            float z = d * g_wsum[j] + b_decay[j];
            float gamma = expf(-fmaxf(z, 0.f));
            float hv = h[(size_t)b*HID + j] * gamma;
            g_hbf[(size_t)b*HW + j] = __float2bfloat16(hv);
            dot += hv * W_reg[j];
        }
    }
    #pragma unroll
    for (int o = 16; o > 0; o >>= 1) dot += __shfl_down_sync(0xffffffffu, dot, o);
    if (lane == 0) {
        float xh = dot + b_reg[0];
        float xo = values[((size_t)b*SEQ_LEN + t)*NF + VARIDX];
        float xv = xo*m + (1.f - m)*xh;
        g_xvar[b] = xv;
        out_imp[b*SEQ_LEN + t] = xv;
        g_numbuf[t][b] = m * fabsf(xo - xh);
        g_denbuf[t][b] = m;
    }
}

// ---------------- cp.async chunk (32 k bf16 = 64B/row) ----------------
__device__ __forceinline__ void issue_chunk(int kt, uint32_t sdst, int rowBase,
                                            int colBlk, int t, int tid) {
    #pragma unroll
    for (int i = 0; i < 2; i++) {           // A: 128 rows x 4 x 16B
        int idx = i*256 + tid, row = idx >> 2, c4 = idx & 3;
        uint32_t dst = sdst + (uint32_t)(row*80 + c4*16);
        const __nv_bfloat16* src;
        if (kt < 13) src = g_hbf + (size_t)(rowBase + row)*HW + kt*32 + c4*8;
        else         src = g_vbf + ((size_t)t*BATCH + rowBase + row)*VW + (kt-13)*32 + c4*8;
        cp16(dst, src);
    }
    #pragma unroll
    for (int i = 0; i < 2; i++) {           // B: 128 cols x 4 x 16B
        int idx = i*256 + tid, col = idx >> 2, c4 = idx & 3;
        uint32_t dst = sdst + (uint32_t)ABYTES + (uint32_t)(col*80 + c4*16);
        cp16(dst, g_Wbf + (size_t)(colBlk*128 + col)*KP + kt*32 + c4*8);
    }
    asm volatile("cp.async.commit_group;" ::: "memory");
}

// ---------------- bf16 mma GEMM (ldmatrix, 4-stage) + fused LSTM epilogue ----------------
// CTA 128x128 packed cols; 8 warps as 4(M) x 2(N); warp tile m32 x n64.
__global__ void __launch_bounds__(256, 2) k_gemm(int t)
{
    extern __shared__ char smem[];
    uint32_t sb = smem_u32(smem);
    int tid = threadIdx.x;
    int warp = tid >> 5, lane = tid & 31, q = lane & 3, rq = lane >> 2;
    int wm = warp & 3, wn = warp >> 2;
    int rowBase = blockIdx.y * 128;
    int colBlk = blockIdx.x;
    float* h_out = g_hbuf[(t + 1) & 1];

    // per-lane LDSM row addresses (conflict-free: 80B row stride)
    int l8 = lane & 7, lb = (lane >> 3) & 1, lh = lane >> 4;
    uint32_t aAddr = sb + (uint32_t)((wm*32 + l8 + lb*8)*80 + lh*16);
    uint32_t bAddr = sb + (uint32_t)(ABYTES + (wn*64 + l8 + lb*8)*80 + lh*16);

    float acc[2][8][4];
    #pragma unroll
    for (int mi = 0; mi < 2; mi++)
        #pragma unroll
        for (int nf = 0; nf < 8; nf++)
            #pragma unroll
            for (int j = 0; j < 4; j++) acc[mi][nf][j] = 0.f;

    issue_chunk(0, sb + 0*BUFB, rowBase, colBlk, t, tid);
    issue_chunk(1, sb + 1*BUFB, rowBase, colBlk, t, tid);
    issue_chunk(2, sb + 2*BUFB, rowBase, colBlk, t, tid);

    #pragma unroll 1
    for (int kt = 0; kt < NCH; kt++) {
        int buf = kt & 3;
        if (kt < NCH-2)       asm volatile("cp.async.wait_group 2;" ::: "memory");
        else if (kt == NCH-2) asm volatile("cp.async.wait_group 1;" ::: "memory");
        else                  asm volatile("cp.async.wait_group 0;" ::: "memory");
        __syncthreads();
        if (kt + 3 < NCH)
            issue_chunk(kt+3, sb + (uint32_t)(((kt+3) & 3)*BUFB), rowBase, colBlk, t, tid);
        if (kt == NCH-1) {
            if (tid < 128) {  // patch xvar: chunk-38 local bf16 index 11 -> byte 22
                *(__nv_bfloat16*)(smem + buf*BUFB + tid*80 + 22) =
                    __float2bfloat16(g_xvar[rowBase + tid]);
            }
            __syncthreads();
        }
        uint32_t ab = aAddr + (uint32_t)(buf*BUFB);
        uint32_t bb = bAddr + (uint32_t)(buf*BUFB);
        #pragma unroll
        for (int s = 0; s < 2; s++) {
            uint32_t a[2][4];
            #pragma unroll
            for (int mi = 0; mi < 2; mi++)
                ldsm4(a[mi][0], a[mi][1], a[mi][2], a[mi][3], ab + mi*1280 + s*32);
            #pragma unroll
            for (int nfp = 0; nfp < 4; nfp++) {
                // b0 = n[0..7]k[0..7], b1 = n[8..15]k[0..7], b2 = n[0..7]k[8..15], b3 = n[8..15]k[8..15]
                uint32_t b0, b1, b2, b3;
                ldsm4(b0, b1, b2, b3, bb + nfp*1280 + s*32);
                #pragma unroll
                for (int mi = 0; mi < 2; mi++) {
                    // mma B operand needs {k-lo, k-hi} of the SAME n-octet: (b0,b2) and (b1,b3)
                    mma_bf16(acc[mi][nfp*2+0], a[mi][0], a[mi][1], a[mi][2], a[mi][3], b0, b2);
                    mma_bf16(acc[mi][nfp*2+1], a[mi][0], a[mi][1], a[mi][2], a[mi][3], b1, b3);
                }
            }
        }
    }

    // ---- fused LSTM epilogue (identical mapping to R4) ----
    int row_b = rowBase + wm*32 + rq;
    #pragma unroll
    for (int sbx = 0; sbx < 2; sbx++) {
        int u0 = colBlk*32 + wn*16 + sbx*8 + 2*q;
        if (u0 >= HID) continue;
        float2 bi = *(const float2*)&g_bias[u0];
        float2 bf_ = *(const float2*)&g_bias[HID + u0];
        float2 bg = *(const float2*)&g_bias[2*HID + u0];
        float2 bo = *(const float2*)&g_bias[3*HID + u0];
        #pragma unroll
        for (int mi = 0; mi < 2; mi++) {
            #pragma unroll
            for (int r = 0; r < 2; r++) {
                int row = row_b + mi*16 + r*8;
                int e = r*2;
                float ig0 = acc[mi][0+sbx][e]   + bi.x, ig1 = acc[mi][0+sbx][e+1] + bi.y;
                float fg0 = acc[mi][2+sbx][e]   + bf_.x, fg1 = acc[mi][2+sbx][e+1] + bf_.y;
                float gg0 = acc[mi][4+sbx][e]   + bg.x, gg1 = acc[mi][4+sbx][e+1] + bg.y;
                float og0 = acc[mi][6+sbx][e]   + bo.x, og1 = acc[mi][6+sbx][e+1] + bo.y;
                float2 cin = *(float2*)&g_c[(size_t)row*HID + u0];
                float si0 = 1.f/(1.f + expf(-ig0)), si1 = 1.f/(1.f + expf(-ig1));
                float sf0 = 1.f/(1.f + expf(-fg0)), sf1 = 1.f/(1.f + expf(-fg1));
                float so0 = 1.f/(1.f + expf(-og0)), so1 = 1.f/(1.f + expf(-og1));
                float c0 = sf0*cin.x + si0*tanhf(gg0);
                float c1 = sf1*cin.y + si1*tanhf(gg1);
                *(float2*)&g_c[(size_t)row*HID + u0]   = make_float2(c0, c1);
                *(float2*)&h_out[(size_t)row*HID + u0] = make_float2(so0*tanhf(c0), so1*tanhf(c1));
            }
        }
    }
}

// ---------------- deterministic loss reduction ----------------
__global__ void k_loss1() {
    int t = blockIdx.x, tid = threadIdx.x;
    float sn = 0.f, sd = 0.f;
    for (int b = tid; b < BATCH; b += 256) { sn += g_numbuf[t][b]; sd += g_denbuf[t][b]; }
    __shared__ float rn[256], rd[256];
    rn[tid] = sn; rd[tid] = sd;
    __syncthreads();
    for (int o = 128; o > 0; o >>= 1) {
        if (tid < o) { rn[tid] += rn[tid+o]; rd[tid] += rd[tid+o]; }
        __syncthreads();
    }
    if (tid == 0) g_stepw[t] = rn[0] / (rd[0] + 1e-5f);
}
__global__ void k_loss2(float* __restrict__ out) {
    if (threadIdx.x == 0 && blockIdx.x == 0) {
        float s = 0.f;
        for (int t = 0; t < SEQ_LEN; t++) s += g_stepw[t];
        out[0] = s / (float)SEQ_LEN;
    }
}

extern "C" void kernel_launch(void* const* d_in, const int* in_sizes, int n_in,
                              void* d_out, int out_size) {
    const float* values  = (const float*)d_in[0];
    const float* masks   = (const float*)d_in[1];
    const float* deltas  = (const float*)d_in[2];
    const float* W_decay = (const float*)d_in[3];
    const float* b_decay = (const float*)d_in[4];
    const float* W_reg   = (const float*)d_in[5];
    const float* b_reg   = (const float*)d_in[6];
    const float* W_ih    = (const float*)d_in[7];
    const float* W_hh    = (const float*)d_in[8];
    const float* b_ih    = (const float*)d_in[9];
    const float* b_hh    = (const float*)d_in[10];
    float* out = (float*)d_out;
    float* out_imp = out + 1;

    cudaFuncSetAttribute(k_gemm, cudaFuncAttributeMaxDynamicSharedMemorySize, SMEMSZ);

    k_init<<<(BATCH*HW + 255)/256, 256>>>(W_decay);
    k_vpack<<<(int)(((size_t)SEQ_LEN*BATCH*VW + 255)/256), 256>>>(values, masks);
    k_pack<<<(int)(((size_t)NPCOL*KP + 255)/256), 256>>>(W_ih, W_hh, b_ih, b_hh);
    for (int t = 0; t < SEQ_LEN; t++) {
        k_decay<<<BATCH/8, 256>>>(values, masks, deltas, b_decay, W_reg, b_reg, out_imp, t);
        dim3 grid(NPCOL/128, BATCH/128);   // (13, 64)
        k_gemm<<<grid, 256, SMEMSZ>>>(t);
    }
    k_loss1<<<SEQ_LEN, 256>>>();
    k_loss2<<<1, 32>>>(out);
}